// round 2
// baseline (speedup 1.0000x reference)
#include <cuda_runtime.h>

#define NB 4
#define NT 4096
#define DE 1024
#define DH 64
#define BT (NB*NT)   // 16384 rows

// Scratch for projected Q, K, V (4 MB each)
__device__ float g_Q[(size_t)BT * DH];
__device__ float g_K[(size_t)BT * DH];
__device__ float g_V[(size_t)BT * DH];

__device__ __forceinline__ float ex2(float x) {
    float y;
    asm("ex2.approx.ftz.f32 %0, %1;" : "=f"(y) : "f"(x));
    return y;
}

// ===================== Kernel 1: QKV projection =====================
// out[row, h] = sum_e x[row, e] * W[h, e]
// M=16384, N=64 (per W), K=1024. Tile: BM=128, BN=64, BK=32; 256 threads, 8x4/thread.
__global__ __launch_bounds__(256) void qkv_kernel(
    const float* __restrict__ x,
    const float* __restrict__ Wk,
    const float* __restrict__ Wq,
    const float* __restrict__ Wv)
{
    __shared__ float Xs[32][132];  // [k][row], padded
    __shared__ float Ws[32][68];   // [k][col], padded

    const float* __restrict__ W;
    float* out;
    const int sel = blockIdx.y;
    if (sel == 0)      { W = Wq; out = g_Q; }
    else if (sel == 1) { W = Wk; out = g_K; }
    else               { W = Wv; out = g_V; }

    const int tid = threadIdx.x;
    const int tx = tid & 15;        // 0..15 -> 4 cols each
    const int ty = tid >> 4;        // 0..15 -> 8 rows each
    const int rowBase = blockIdx.x * 128;

    float acc[8][4];
#pragma unroll
    for (int i = 0; i < 8; i++)
#pragma unroll
        for (int j = 0; j < 4; j++) acc[i][j] = 0.f;

    for (int kc = 0; kc < DE; kc += 32) {
        // Load X tile (128x32) transposed into Xs[k][row]
#pragma unroll
        for (int i = 0; i < 4; i++) {
            int idx4 = tid + i * 256;          // 0..1023 float4s
            int row = idx4 >> 3;               // 0..127
            int kq  = idx4 & 7;                // 0..7
            float4 v = *(const float4*)(x + (size_t)(rowBase + row) * DE + kc + kq * 4);
            Xs[kq*4+0][row] = v.x;
            Xs[kq*4+1][row] = v.y;
            Xs[kq*4+2][row] = v.z;
            Xs[kq*4+3][row] = v.w;
        }
        // Load W tile (64x32) transposed into Ws[k][col]
#pragma unroll
        for (int i = 0; i < 2; i++) {
            int idx4 = tid + i * 256;          // 0..511
            int wrow = idx4 >> 3;              // 0..63
            int kq   = idx4 & 7;
            float4 v = *(const float4*)(W + (size_t)wrow * DE + kc + kq * 4);
            Ws[kq*4+0][wrow] = v.x;
            Ws[kq*4+1][wrow] = v.y;
            Ws[kq*4+2][wrow] = v.z;
            Ws[kq*4+3][wrow] = v.w;
        }
        __syncthreads();
#pragma unroll 8
        for (int k = 0; k < 32; k++) {
            float4 a0 = *(const float4*)&Xs[k][ty*8];
            float4 a1 = *(const float4*)&Xs[k][ty*8+4];
            float4 bv = *(const float4*)&Ws[k][tx*4];
            float a[8] = {a0.x, a0.y, a0.z, a0.w, a1.x, a1.y, a1.z, a1.w};
#pragma unroll
            for (int i = 0; i < 8; i++) {
                acc[i][0] = fmaf(a[i], bv.x, acc[i][0]);
                acc[i][1] = fmaf(a[i], bv.y, acc[i][1]);
                acc[i][2] = fmaf(a[i], bv.z, acc[i][2]);
                acc[i][3] = fmaf(a[i], bv.w, acc[i][3]);
            }
        }
        __syncthreads();
    }
#pragma unroll
    for (int i = 0; i < 8; i++) {
        float4 v = make_float4(acc[i][0], acc[i][1], acc[i][2], acc[i][3]);
        *(float4*)(out + (size_t)(rowBase + ty*8 + i) * DH + tx*4) = v;
    }
}

// ===================== Kernel 2: causal flash attention =====================
// BQ = BKV = 64, 256 threads (16x16), 4x4 per-thread tiles.
// smem = Qs(16KB) + Xb(K then P, 16KB) + Vs(16KB) = exactly 48KB static.
// Each block handles q-tiles (x) and (63-x): 65 KV-tiles total -> perfect balance.
#define SCL (0.125f * 1.4426950408889634f)   // 1/sqrt(64) * log2(e)

__global__ __launch_bounds__(256) void attn_kernel(float* __restrict__ out)
{
    __shared__ float Qs[64*64];  // [h][i] transposed
    __shared__ float Xb[64*64];  // K as [h][j], then P as [i][j]
    __shared__ float Vs[64*64];  // [t][h] natural

    const int tid = threadIdx.x;
    const int tx = tid & 15;   // j / d groups of 4
    const int ty = tid >> 4;   // i groups of 4
    const size_t bb = (size_t)blockIdx.y * NT;

#pragma unroll 1
    for (int pass = 0; pass < 2; pass++) {
        const int qt = (pass == 0) ? (int)blockIdx.x : 63 - (int)blockIdx.x;
        const int qbase = qt * 64;

        // Load Q tile transposed, pre-scaled by 1/sqrt(d)*log2e
#pragma unroll
        for (int i = 0; i < 4; i++) {
            int idx4 = tid + i * 256;
            int r  = idx4 >> 4;     // 0..63 token
            int hq = idx4 & 15;     // float4 within head dim
            float4 v = *(const float4*)(g_Q + (bb + qbase + r) * DH + hq * 4);
            Qs[(hq*4+0)*64 + r] = v.x * SCL;
            Qs[(hq*4+1)*64 + r] = v.y * SCL;
            Qs[(hq*4+2)*64 + r] = v.z * SCL;
            Qs[(hq*4+3)*64 + r] = v.w * SCL;
        }

        float o[4][4], m[4], l[4];
#pragma unroll
        for (int i = 0; i < 4; i++) {
            m[i] = -1e30f; l[i] = 0.f;
#pragma unroll
            for (int j = 0; j < 4; j++) o[i][j] = 0.f;
        }

        for (int kt = 0; kt <= qt; kt++) {
            const int kbase = kt * 64;
            // Load K (transposed into Xb) and V (natural into Vs)
#pragma unroll
            for (int i = 0; i < 4; i++) {
                int idx4 = tid + i * 256;
                int r  = idx4 >> 4;
                int hq = idx4 & 15;
                float4 v = *(const float4*)(g_K + (bb + kbase + r) * DH + hq * 4);
                Xb[(hq*4+0)*64 + r] = v.x;
                Xb[(hq*4+1)*64 + r] = v.y;
                Xb[(hq*4+2)*64 + r] = v.z;
                Xb[(hq*4+3)*64 + r] = v.w;
                float4 w = *(const float4*)(g_V + (bb + kbase + r) * DH + hq * 4);
                *(float4*)&Vs[r*64 + hq*4] = w;
            }
            __syncthreads();   // tiles (and Qs on first iter) visible

            // S tile: s[ii][jj] = sum_h Qs[h][4ty+ii] * K[h][4tx+jj]
            float s[4][4];
#pragma unroll
            for (int ii = 0; ii < 4; ii++)
#pragma unroll
                for (int jj = 0; jj < 4; jj++) s[ii][jj] = 0.f;
#pragma unroll 8
            for (int h = 0; h < 64; h++) {
                float4 qa = *(const float4*)&Qs[h*64 + ty*4];
                float4 kb = *(const float4*)&Xb[h*64 + tx*4];
                float a[4] = {qa.x, qa.y, qa.z, qa.w};
#pragma unroll
                for (int ii = 0; ii < 4; ii++) {
                    s[ii][0] = fmaf(a[ii], kb.x, s[ii][0]);
                    s[ii][1] = fmaf(a[ii], kb.y, s[ii][1]);
                    s[ii][2] = fmaf(a[ii], kb.z, s[ii][2]);
                    s[ii][3] = fmaf(a[ii], kb.w, s[ii][3]);
                }
            }

            // Causal mask (only on the diagonal tile)
            if (kt == qt) {
#pragma unroll
                for (int ii = 0; ii < 4; ii++)
#pragma unroll
                    for (int jj = 0; jj < 4; jj++)
                        if (tx*4 + jj > ty*4 + ii) s[ii][jj] = -1e30f;
            }

            __syncthreads();  // all threads done reading Xb as K

            // Online softmax; write P into Xb[i][j]
#pragma unroll
            for (int ii = 0; ii < 4; ii++) {
                float tmax = fmaxf(fmaxf(s[ii][0], s[ii][1]), fmaxf(s[ii][2], s[ii][3]));
#pragma unroll
                for (int w = 1; w < 16; w <<= 1)
                    tmax = fmaxf(tmax, __shfl_xor_sync(0xffffffffu, tmax, w));
                float mn = fmaxf(m[ii], tmax);
                float corr = ex2(m[ii] - mn);
                m[ii] = mn;
                float rs = 0.f;
#pragma unroll
                for (int jj = 0; jj < 4; jj++) {
                    float p = ex2(s[ii][jj] - mn);
                    s[ii][jj] = p;
                    rs += p;
                }
#pragma unroll
                for (int w = 1; w < 16; w <<= 1)
                    rs += __shfl_xor_sync(0xffffffffu, rs, w);
                l[ii] = l[ii] * corr + rs;
#pragma unroll
                for (int dd = 0; dd < 4; dd++) o[ii][dd] *= corr;
                *(float4*)&Xb[(ty*4+ii)*64 + tx*4] =
                    make_float4(s[ii][0], s[ii][1], s[ii][2], s[ii][3]);
            }
            __syncthreads();  // P visible

            // O += P @ V
#pragma unroll 8
            for (int kv = 0; kv < 64; kv++) {
                float4 vv = *(const float4*)&Vs[kv*64 + tx*4];
                float pa[4];
#pragma unroll
                for (int ii = 0; ii < 4; ii++) pa[ii] = Xb[(ty*4+ii)*64 + kv];
#pragma unroll
                for (int ii = 0; ii < 4; ii++) {
                    o[ii][0] = fmaf(pa[ii], vv.x, o[ii][0]);
                    o[ii][1] = fmaf(pa[ii], vv.y, o[ii][1]);
                    o[ii][2] = fmaf(pa[ii], vv.z, o[ii][2]);
                    o[ii][3] = fmaf(pa[ii], vv.w, o[ii][3]);
                }
            }
            __syncthreads();  // done with Xb/Vs before next tile load
        }

        // Epilogue: normalize and store
#pragma unroll
        for (int ii = 0; ii < 4; ii++) {
            float inv = 1.f / l[ii];
            float4 v = make_float4(o[ii][0]*inv, o[ii][1]*inv, o[ii][2]*inv, o[ii][3]*inv);
            *(float4*)(out + (bb + qbase + ty*4 + ii) * DH + tx*4) = v;
        }
    }
}

extern "C" void kernel_launch(void* const* d_in, const int* in_sizes, int n_in,
                              void* d_out, int out_size) {
    const float* x  = (const float*)d_in[0];
    const float* Wk = (const float*)d_in[1];
    const float* Wq = (const float*)d_in[2];
    const float* Wv = (const float*)d_in[3];
    float* out = (float*)d_out;

    qkv_kernel<<<dim3(BT/128, 3), 256>>>(x, Wk, Wq, Wv);
    attn_kernel<<<dim3(32, NB), 256>>>(out);

    (void)in_sizes; (void)n_in; (void)out_size;
}